// round 3
// baseline (speedup 1.0000x reference)
#include <cuda_runtime.h>
#include <cuda_fp16.h>

// Inputs (harness upcasts f16 arrays to f32):
//   x:      [N=16384, DIM=4096] f32 (f16-valued)
//   pairs:  [KROT=8, DIM]       int32 (same local pattern tiled per 128-group)
//   theta:  [KROT, DIM/2]       f32 (f16-valued)
//   scales: [1, DIM]            f32 (f16-valued)
//   out:    [N, DIM]            f32
// Reference rounds to f16 after EVERY op -> use *_rn intrinsics (no HFMA2 contraction).
#define DIMV   4096
#define KROT   8
#define NPAIR  2048
#define GRP    128
#define NGRP   32
#define ILG    64
#define ROWS   4

// g_cs layout: [k][il*32 + g] -> warp (lanes = g) reads one coalesced 128B line.
__device__ __half2  g_cs[KROT * NPAIR];
__device__ unsigned g_ab[KROT * ILG];

struct __align__(8) H4 { __half2 r01, r23; };   // 4 rows of one channel

// XOR swizzle: conflict-free when lanes vary g at fixed channel c.
__device__ __forceinline__ int swz(int c, int g) {
    return c * NGRP + (g ^ (c & 31));
}

__global__ void prep_kernel(const float* __restrict__ theta,
                            const int* __restrict__ pairs) {
    int idx = blockIdx.x * blockDim.x + threadIdx.x;
    if (idx < KROT * NPAIR) {
        int k  = idx >> 11;
        int i  = idx & (NPAIR - 1);
        int g  = i >> 6;
        int il = i & (ILG - 1);
        float t = theta[idx];
        __half c = __float2half(cosf(t));
        __half s = __float2half(sinf(t));
        g_cs[(k << 11) + il * NGRP + g] = __halves2half2(c, s);
    }
    if (idx < KROT * ILG) {
        int k  = idx >> 6;
        int il = idx & (ILG - 1);
        int a = pairs[k * DIMV + 2 * il];
        int b = pairs[k * DIMV + 2 * il + 1];
        g_ab[idx] = (unsigned)(a | (b << 8));
    }
}

__global__ void __launch_bounds__(256)
rot_kernel(const float* __restrict__ x,
           const float* __restrict__ scales,
           float* __restrict__ out) {
    __shared__ H4 s[GRP * NGRP];   // 32KB: all 4 rows, channel-major

    const int tid = threadIdx.x;
    const size_t base = (size_t)blockIdx.x * ROWS * DIMV;

    // ---- Load: global f32 float4 (coalesced) -> shared f16 (channel-major, 8B words) ----
    #pragma unroll
    for (int m = 0; m < 4; m++) {
        int d0 = (tid + m * 256) * 4;          // 4 consecutive channels
        int c = d0 & (GRP - 1), g = d0 >> 7;
        float4 v0 = *(const float4*)(x + base + d0);
        float4 v1 = *(const float4*)(x + base + DIMV + d0);
        float4 v2 = *(const float4*)(x + base + 2 * DIMV + d0);
        float4 v3 = *(const float4*)(x + base + 3 * DIMV + d0);
        const float* p0 = &v0.x; const float* p1 = &v1.x;
        const float* p2 = &v2.x; const float* p3 = &v3.x;
        #pragma unroll
        for (int j = 0; j < 4; j++) {
            H4 w;
            w.r01 = __floats2half2_rn(p0[j], p1[j]);   // exact: inputs are f16-valued
            w.r23 = __floats2half2_rn(p2[j], p3[j]);
            s[swz(c + j, g)] = w;                       // STS.64
        }
    }
    __syncthreads();

    // ---- Rotation: warp lanes = 32 groups (conflict-free), warp = 8 local pairs ----
    const int g = tid & 31;
    const int ilbase = (tid >> 5) * 8;

    #pragma unroll
    for (int k = 0; k < KROT; k++) {
        #pragma unroll
        for (int m = 0; m < 8; m++) {
            int il = ilbase + m;
            unsigned ab = g_ab[(k << 6) + il];            // warp-uniform broadcast
            int a = ab & 255, b = ab >> 8;
            __half2 cs = g_cs[(k << 11) + il * NGRP + g]; // coalesced 128B line
            __half2 hc = __half2half2(__low2half(cs));
            __half2 hs = __half2half2(__high2half(cs));
            int wa = swz(a, g), wb = swz(b, g);
            H4 ua = s[wa], ub = s[wb];                    // LDS.64 x2
            H4 ra, rb;
            // Per-op f16 rounding, contraction forbidden (_rn), reference order.
            ra.r01 = __hsub2_rn(__hmul2_rn(hc, ua.r01), __hmul2_rn(hs, ub.r01));
            rb.r01 = __hadd2_rn(__hmul2_rn(hs, ua.r01), __hmul2_rn(hc, ub.r01));
            ra.r23 = __hsub2_rn(__hmul2_rn(hc, ua.r23), __hmul2_rn(hs, ub.r23));
            rb.r23 = __hadd2_rn(__hmul2_rn(hs, ua.r23), __hmul2_rn(hc, ub.r23));
            s[wa] = ra; s[wb] = rb;                       // STS.64 x2
        }
        __syncthreads();   // pairs disjoint within a layer; sync only between layers
    }

    // ---- Store: shared f16 -> global f32 float4, channel scaling in f16 (_rn) ----
    #pragma unroll
    for (int m = 0; m < 4; m++) {
        int d0 = (tid + m * 256) * 4;
        int c = d0 & (GRP - 1), gg = d0 >> 7;
        float4 scf = *(const float4*)(scales + d0);
        const float* ps = &scf.x;
        float4 o0, o1, o2, o3;
        float* q0 = &o0.x; float* q1 = &o1.x;
        float* q2 = &o2.x; float* q3 = &o3.x;
        #pragma unroll
        for (int j = 0; j < 4; j++) {
            H4 w = s[swz(c + j, gg)];                     // LDS.64
            __half sc = __float2half(ps[j]);
            q0[j] = __half2float(__hmul_rn(__low2half (w.r01), sc));
            q1[j] = __half2float(__hmul_rn(__high2half(w.r01), sc));
            q2[j] = __half2float(__hmul_rn(__low2half (w.r23), sc));
            q3[j] = __half2float(__hmul_rn(__high2half(w.r23), sc));
        }
        *(float4*)(out + base + d0)            = o0;
        *(float4*)(out + base + DIMV + d0)     = o1;
        *(float4*)(out + base + 2 * DIMV + d0) = o2;
        *(float4*)(out + base + 3 * DIMV + d0) = o3;
    }
}

extern "C" void kernel_launch(void* const* d_in, const int* in_sizes, int n_in,
                              void* d_out, int out_size) {
    const float* x      = (const float*)d_in[0];
    const int*   pairs  = (const int*)d_in[1];
    const float* theta  = (const float*)d_in[2];
    const float* scales = (const float*)d_in[3];
    (void)n_in;

    int N = in_sizes[0] / DIMV;   // 16384

    prep_kernel<<<(KROT * NPAIR + 255) / 256, 256>>>(theta, pairs);
    rot_kernel<<<N / ROWS, 256>>>(x, scales, (float*)d_out);
    (void)out_size;
}